// round 10
// baseline (speedup 1.0000x reference)
#include <cuda_runtime.h>

// Analytic collapse of the 4-qubit, 2-layer circuit:
//   out[i] = sigmoid( (cos(x0)*cos(x1)*cos(x3) + 1) * 0.5 )
// RZ phases (weights) cancel in |amp|^2; two CNOT-ring layers compose to a
// GF(2)-linear bit map with final q0 parity = b0^b1^b3 of the initial basis
// index, so <Z0> = cos(x0)cos(x1)cos(x3) for the RY product state.
//
// Accuracy: __cosf/__expf/__fdividef path measured at rel_err ~5e-8 (R5).
// Schedule: 2 rows/thread, 1024 blocks x 256 threads = 262144 threads ->
// single wave on 148 SMs, avoiding the wave transition that bounded R6.

__device__ __forceinline__ float row_val(float4 a) {
    float z = __cosf(a.x) * __cosf(a.y) * __cosf(a.w);
    float t = fmaf(z, 0.5f, 0.5f);            // (z+1)/2 in [0,1]
    float e = __expf(-t);
    return __fdividef(1.0f, 1.0f + e);        // MUFU.RCP path, ~ulp-accurate here
}

__global__ __launch_bounds__(256)
void dqc_kernel(const float4* __restrict__ in, float2* __restrict__ out,
                int npair, int n) {
    int i = blockIdx.x * blockDim.x + threadIdx.x;
    if (i < npair) {
        float4 a = in[2 * i];                 // independent loads, MLP=2
        float4 b = in[2 * i + 1];
        float2 r;
        r.x = row_val(a);
        r.y = row_val(b);
        out[i] = r;
    }
    // odd-B tail (never hit for B = 2^19)
    if ((n & 1) && i == 0) {
        reinterpret_cast<float*>(out)[n - 1] = row_val(in[n - 1]);
    }
}

extern "C" void kernel_launch(void* const* d_in, const int* in_sizes, int n_in,
                              void* d_out, int out_size) {
    const float4* inputs = (const float4*)d_in[0];   // [B,4] float32 rows
    float* out = (float*)d_out;                      // [B] float32
    int B = in_sizes[0] / 4;
    int npair = B >> 1;                              // 262144 for B=2^19
    int threads = 256;
    int blocks = (npair + threads - 1) / threads;    // -> 1024 blocks
    if (blocks < 1) blocks = 1;
    dqc_kernel<<<blocks, threads>>>(inputs, (float2*)out, npair, B);
}

// round 14
// speedup vs baseline: 1.0047x; 1.0047x over previous
#include <cuda_runtime.h>

// Analytic collapse of the 4-qubit, 2-layer circuit:
//   out[i] = sigmoid( (cos(x0)*cos(x1)*cos(x3) + 1) * 0.5 )
// RZ phases (weights) cancel in |amp|^2; two CNOT-ring layers compose to a
// GF(2)-linear bit map with final q0 parity = b0^b1^b3 of the initial basis
// index, so <Z0> = cos(x0)cos(x1)cos(x3) for the RY product state.
//
// Accuracy: __cosf/__expf/__fdividef path, measured rel_err ~5e-8.
// Schedule experiment (retry): same 524288 threads as R6 but packed into
// 512 CTAs of 1024 threads (2 resident CTAs/SM at regs<=16) to test whether
// CTA dispatch count is part of the ~3.5us non-memory floor.
// Streaming cache hints: inputs/outputs have zero reuse.

__device__ __forceinline__ float row_val(float4 a) {
    float z = __cosf(a.x) * __cosf(a.y) * __cosf(a.w);
    float t = fmaf(z, 0.5f, 0.5f);            // (z+1)/2 in [0,1]
    float e = __expf(-t);
    return __fdividef(1.0f, 1.0f + e);
}

__global__ __launch_bounds__(1024)
void dqc_kernel(const float4* __restrict__ in, float* __restrict__ out, int n) {
    int i = blockIdx.x * blockDim.x + threadIdx.x;
    int stride = gridDim.x * blockDim.x;
    for (; i < n; i += stride) {
        float4 a = __ldcs(&in[i]);            // evict-first: no reuse
        __stcs(&out[i], row_val(a));
    }
}

extern "C" void kernel_launch(void* const* d_in, const int* in_sizes, int n_in,
                              void* d_out, int out_size) {
    const float4* inputs = (const float4*)d_in[0];   // [B,4] float32 rows
    float* out = (float*)d_out;                      // [B] float32
    int B = in_sizes[0] / 4;
    int threads = 1024;
    int blocks = (B + threads - 1) / threads;        // B=2^19 -> 512 blocks
    if (blocks < 1) blocks = 1;
    dqc_kernel<<<blocks, threads>>>(inputs, out, B);
}